// round 5
// baseline (speedup 1.0000x reference)
#include <cuda_runtime.h>
#include <cuda_bf16.h>
#include <cstdint>

#define NROWS 262144
#define DD 128
#define HH 16
#define EE 21

#define THREADS 256
#define HALF_T 128
#define RPT 8                    // rows per thread (each half covers all 1024 rows)
#define M_TILE 1024
#define CHUNK_D 16
#define NPHASE 8                 // 128/16
#define GRID_MAIN 148

#define XBUF_BYTES (M_TILE * CHUNK_D * 4)     // 65536
#define WB_FLOATS (DD * HH)                   // 2048
#define WB_BYTES (WB_FLOATS * 4)              // 8192
// 3 x-buffers + 2 weight buffers + 2 wx + 2 sRow + psum
#define SMEM_BYTES (3 * XBUF_BYTES + 2 * WB_BYTES + 2 * 160 + 2 * M_TILE * 4 + M_TILE * 4)

__device__ int g_counts[EE];
__device__ int g_cursor[EE];
__device__ int g_offsets[EE + 1];
__device__ int g_tileOff[EE + 1];
__device__ int g_numTiles;
__device__ int g_perm[NROWS];

// ---------------- K1: histogram (int4 vectorized) ----------------
__global__ void k_hist(const int* __restrict__ sid) {
    __shared__ int sh[EE];
    int tid = threadIdx.x;
    if (tid < EE) sh[tid] = 0;
    __syncthreads();
    int4 v = ((const int4*)sid)[blockIdx.x * blockDim.x + tid];
    atomicAdd(&sh[v.x], 1);
    atomicAdd(&sh[v.y], 1);
    atomicAdd(&sh[v.z], 1);
    atomicAdd(&sh[v.w], 1);
    __syncthreads();
    if (tid < EE) atomicAdd(&g_counts[tid], sh[tid]);
}

// ---------------- K2: warp scan (+ zero counts for next replay) ----------
__global__ void k_scan() {
    int t = threadIdx.x;
    int c  = (t < EE) ? g_counts[t] : 0;
    int tl = (c + M_TILE - 1) / M_TILE;
    int ic = c, it = tl;
    #pragma unroll
    for (int d = 1; d < 32; d <<= 1) {
        int vc = __shfl_up_sync(0xFFFFFFFFu, ic, d);
        int vt = __shfl_up_sync(0xFFFFFFFFu, it, d);
        if (t >= d) { ic += vc; it += vt; }
    }
    if (t < EE) {
        g_offsets[t] = ic - c;
        g_cursor[t]  = ic - c;
        g_tileOff[t] = it - tl;
        g_counts[t]  = 0;
    }
    int totC = __shfl_sync(0xFFFFFFFFu, ic, EE - 1);
    int totT = __shfl_sync(0xFFFFFFFFu, it, EE - 1);
    if (t == 0) {
        g_offsets[EE] = totC;
        g_tileOff[EE] = totT;
        g_numTiles = totT;
    }
}

// ---------------- K3: scatter ----------------
__global__ void k_scatter(const int* __restrict__ sid) {
    __shared__ int sHist[EE];
    __shared__ int sBase[EE];
    int tid = threadIdx.x;
    if (tid < EE) sHist[tid] = 0;
    __syncthreads();
    int gid = blockIdx.x * blockDim.x + tid;
    int e = sid[gid];
    int myIdx = atomicAdd(&sHist[e], 1);
    __syncthreads();
    if (tid < EE) sBase[tid] = atomicAdd(&g_cursor[tid], sHist[tid]);
    __syncthreads();
    g_perm[sBase[e] + myIdx] = gid;
}

// ---------------- K4: persistent pipelined expert MLP ----------------
__device__ __forceinline__ void cp_async16(uint32_t dst, const void* src) {
    asm volatile("cp.async.cg.shared.global [%0], [%1], 16;\n" :: "r"(dst), "l"(src));
}
__device__ __forceinline__ void cp_async4(uint32_t dst, const void* src) {
    asm volatile("cp.async.ca.shared.global [%0], [%1], 4;\n" :: "r"(dst), "l"(src));
}
#define CP_COMMIT() asm volatile("cp.async.commit_group;" ::: "memory")
#define CP_WAIT1()  asm volatile("cp.async.wait_group 1;" ::: "memory")
#define FMA2(acc, a, b) asm("fma.rn.f32x2 %0, %1, %2, %0;" : "+l"(acc) : "l"(a), "l"(b))

__device__ __forceinline__ unsigned long long bcast2(float f) {
    unsigned long long r;
    asm("mov.b64 %0, {%1,%1};" : "=l"(r) : "f"(f));
    return r;
}

__global__ __launch_bounds__(THREADS, 1)
void k_main(const float* __restrict__ x,
            const float* __restrict__ W1,
            const float* __restrict__ b1,
            const float* __restrict__ W2,
            const float* __restrict__ b2,
            float* __restrict__ out)
{
    extern __shared__ float smem[];
    float* xs   = smem;                                  // 3 x 64KB
    float* wb   = xs + 3 * (XBUF_BYTES / 4);             // 2 x [128][16]
    float* wx   = wb + 2 * WB_FLOATS;                    // 2 x 40 (b1,w2,b2)
    int*  sRow  = (int*)(wx + 2 * 40);                   // 2 x 1024
    float* psum = (float*)(sRow + 2 * M_TILE);           // 1024

    int nT = g_numTiles;
    int q = (nT + GRID_MAIN - 1) / GRID_MAIN;
    int t0 = blockIdx.x * q;
    int t1 = t0 + q; if (t1 > nT) t1 = nT;
    if (t0 >= t1) return;

    int tid = threadIdx.x;
    int half = tid >> 7;             // 0: h[0:8], 1: h[8:16]
    int tt = tid & 127;              // row-group index
    uint32_t xs_sh = (uint32_t)__cvta_generic_to_shared(xs);
    uint32_t wb_sh = (uint32_t)__cvta_generic_to_shared(wb);
    uint32_t wx_sh = (uint32_t)__cvta_generic_to_shared(wx);

    auto tile_meta = [&](int t, int& e, int& rs, int& v) {
        e = 0;
        #pragma unroll
        for (int j = 1; j < EE; j++)
            if (t >= g_tileOff[j]) e = j;
        int ti = t - g_tileOff[e];
        rs = g_offsets[e] + ti * M_TILE;
        v = g_offsets[e + 1] - rs;
        if (v > M_TILE) v = M_TILE;
    };
    auto stage_w = [&](int e, int par) {
        const float* W1e = W1 + (size_t)e * WB_FLOATS;
        uint32_t dst = wb_sh + (uint32_t)par * WB_BYTES;
        #pragma unroll
        for (int m = 0; m < 2; m++) {
            int s = tid + m * THREADS;
            cp_async16(dst + (uint32_t)s * 16u, W1e + s * 4);
        }
        uint32_t xdst = wx_sh + (uint32_t)par * 160u;
        if (tid < 4)       cp_async16(xdst + tid * 16u, b1 + e * HH + tid * 4);
        else if (tid < 8)  cp_async16(xdst + 64u + (tid - 4) * 16u, W2 + e * HH + (tid - 4) * 4);
        else if (tid == 8) cp_async4(xdst + 128u, b2 + e);
    };
    // stage k-chunk c2 of tile whose rows live in sRow[p2] into ring buffer buf
    auto stage_x = [&](int c2, int p2, int buf) {
        const int* rp = sRow + p2 * M_TILE;
        uint32_t bb = xs_sh + (uint32_t)buf * XBUF_BYTES;
        const float* xc = x + c2 * CHUNK_D;
        #pragma unroll
        for (int m = 0; m < 16; m++) {
            int idx = tid + m * THREADS;
            int r = idx >> 2, s = idx & 3;
            int row = rp[r];
            uint32_t dst = bb + (uint32_t)(r * 64) + (uint32_t)(((s + (r >> 1)) & 3) << 4);
            cp_async16(dst, xc + (size_t)row * DD + s * 4);
        }
    };

    // constant per-thread addressing
    uint32_t roff[RPT];
    #pragma unroll
    for (int k = 0; k < RPT; k++) roff[k] = (uint32_t)(tt + k * HALF_T) * 64u;
    int pk = (tt >> 1) & 3;

    // ---- prologue ----
    int eC, rsC, vC;
    tile_meta(t0, eC, rsC, vC);
    #pragma unroll
    for (int k = 0; k < 4; k++) {
        int r = tid + k * THREADS;
        int idx = (r < vC) ? r : 0;
        sRow[(t0 & 1) * M_TILE + r] = g_perm[rsC + idx];
    }
    __syncthreads();
    int eW0 = -1, eW1 = -1;
    {
        int par0 = t0 & 1;
        stage_w(eC, par0);
        if (par0) eW1 = eC; else eW0 = eC;
        stage_x(0, par0, 0);
        CP_COMMIT();
        stage_x(1, par0, 1);
        CP_COMMIT();
    }

    unsigned long long acc[RPT][4];
    int eN = eC, rsN = 0, vN = vC;
    int rrN[4];

    int nChunk = (t1 - t0) * NPHASE;
    for (int j = 0; j < nChunk; j++) {
        int i = t0 + (j >> 3);
        int c = j & 7;
        int par = i & 1;

        if (c == 0 && (i + 1) < t1) {
            tile_meta(i + 1, eN, rsN, vN);
            #pragma unroll
            for (int k = 0; k < 4; k++) {
                int r = tid + k * THREADS;
                int idx = (r < vN) ? r : 0;
                rrN[k] = g_perm[rsN + idx];
            }
        }

        CP_WAIT1();
        __syncthreads();

        if (c == 1 && (i + 1) < t1) {
            #pragma unroll
            for (int k = 0; k < 4; k++)
                sRow[((i + 1) & 1) * M_TILE + tid + k * THREADS] = rrN[k];
        }

        int j2 = j + 2;
        if (j2 < nChunk) {
            int c2 = j2 & 7;
            bool nextTile = (j2 >> 3) != (j >> 3);
            int p2 = nextTile ? (par ^ 1) : par;
            if (nextTile && c2 == 0) {
                int eOld = p2 ? eW1 : eW0;
                if (eN != eOld) {
                    stage_w(eN, p2);
                    if (p2) eW1 = eN; else eW0 = eN;
                }
            }
            stage_x(c2, p2, j2 % 3);
        }
        CP_COMMIT();

        if (c == 0) {
            #pragma unroll
            for (int k = 0; k < RPT; k++)
                #pragma unroll
                for (int p = 0; p < 4; p++) acc[k][p] = 0ULL;
        }

        // ---- compute chunk: 16 d, 8 rows, 8 h (this thread's half) ----
        {
            uint32_t xb = xs_sh + (uint32_t)(j % 3) * XBUF_BYTES;
            uint32_t wd = wb_sh + (uint32_t)par * WB_BYTES
                        + (uint32_t)(c * CHUNK_D * 64) + (uint32_t)(half * 32);
            #pragma unroll
            for (int g = 0; g < 4; g++) {
                float4 xv[RPT];
                #pragma unroll
                for (int k = 0; k < RPT; k++) {
                    uint32_t a = xb + roff[k] + (uint32_t)(((g + pk) & 3) << 4);
                    asm("ld.shared.v4.f32 {%0,%1,%2,%3}, [%4];"
                        : "=f"(xv[k].x), "=f"(xv[k].y), "=f"(xv[k].z), "=f"(xv[k].w)
                        : "r"(a));
                }
                #pragma unroll
                for (int dd = 0; dd < 4; dd++) {
                    unsigned long long w0, w1, w2, w3;
                    uint32_t wa = wd + (uint32_t)((g * 4 + dd) << 6);
                    asm("ld.shared.v2.b64 {%0,%1}, [%2];" : "=l"(w0), "=l"(w1) : "r"(wa));
                    asm("ld.shared.v2.b64 {%0,%1}, [%2];" : "=l"(w2), "=l"(w3) : "r"(wa + 16));
                    #pragma unroll
                    for (int k = 0; k < RPT; k++) {
                        float xf = (dd == 0) ? xv[k].x : (dd == 1) ? xv[k].y
                                 : (dd == 2) ? xv[k].z : xv[k].w;
                        unsigned long long xd = bcast2(xf);
                        FMA2(acc[k][0], xd, w0);
                        FMA2(acc[k][1], xd, w1);
                        FMA2(acc[k][2], xd, w2);
                        FMA2(acc[k][3], xd, w3);
                    }
                }
            }
        }

        // ---- tile epilogue: combine halves via psum ----
        if (c == 7) {
            const float* wxp = wx + par * 40;
            float b1r[8], w2r[8];
            #pragma unroll
            for (int h = 0; h < 8; h++) {
                b1r[h] = wxp[half * 8 + h];
                w2r[h] = wxp[16 + half * 8 + h];
            }
            float b2v = wxp[32];

            float part[RPT];
            #pragma unroll
            for (int k = 0; k < RPT; k++) {
                float s = 0.0f;
                #pragma unroll
                for (int p = 0; p < 4; p++) {
                    float lo = __uint_as_float((uint32_t)acc[k][p]);
                    float hi = __uint_as_float((uint32_t)(acc[k][p] >> 32));
                    s = fmaf(fmaxf(lo + b1r[2 * p], 0.0f), w2r[2 * p], s);
                    s = fmaf(fmaxf(hi + b1r[2 * p + 1], 0.0f), w2r[2 * p + 1], s);
                }
                part[k] = s;
            }
            if (half == 1) {
                #pragma unroll
                for (int k = 0; k < RPT; k++) psum[tt + k * HALF_T] = part[k];
            }
            __syncthreads();
            if (half == 0) {
                const int* rp = sRow + par * M_TILE;
                #pragma unroll
                for (int k = 0; k < RPT; k++) {
                    int r = tt + k * HALF_T;
                    if (r < vC) {
                        float y = part[k] + psum[r] + b2v;
                        out[rp[r]] = fmaxf(y, 0.0f);
                    }
                }
            }
            eC = eN; vC = vN;
        }
    }
}

extern "C" void kernel_launch(void* const* d_in, const int* in_sizes, int n_in,
                              void* d_out, int out_size)
{
    const float* x   = (const float*)d_in[0];
    const int*   sid = (const int*)d_in[1];
    const float* W1  = (const float*)d_in[2];
    const float* b1  = (const float*)d_in[3];
    const float* W2  = (const float*)d_in[4];
    const float* b2  = (const float*)d_in[5];
    float* out = (float*)d_out;

    static bool attr_set = false;
    if (!attr_set) {
        cudaFuncSetAttribute(k_main, cudaFuncAttributeMaxDynamicSharedMemorySize, SMEM_BYTES);
        attr_set = true;
    }

    k_hist<<<NROWS / 4096, 1024>>>(sid);
    k_scan<<<1, 32>>>();
    k_scatter<<<NROWS / 1024, 1024>>>(sid);
    k_main<<<GRID_MAIN, THREADS, SMEM_BYTES>>>(x, W1, b1, W2, b2, out);
}